// round 11
// baseline (speedup 1.0000x reference)
#include <cuda_runtime.h>
#include <mma.h>
#include <cstdint>

using namespace nvcuda;

#define BB 8
#define DD 512
#define KK 32
#define NN 16384

// 16 MB scratch for soft-assign matrix A[b][n][k] (tf32-rounded by K1)
__device__ float A_buf[(size_t)BB * NN * KK];

__device__ __forceinline__ void cp_async16(void* smem_dst, const void* gmem_src) {
    uint32_t s = (uint32_t)__cvta_generic_to_shared(smem_dst);
    asm volatile("cp.async.cg.shared.global [%0], [%1], 16;\n" :: "r"(s), "l"(gmem_src));
}
__device__ __forceinline__ void cp_commit() {
    asm volatile("cp.async.commit_group;\n" ::: "memory");
}
template<int N>
__device__ __forceinline__ void cp_wait() {
    asm volatile("cp.async.wait_group %0;\n" :: "n"(N) : "memory");
}

// ============================================================================
// Kernel 1: A = softmax_k( s_k * (||x||^2 - 2 x.c_k + ||c_k||^2) )
//   (byte-identical to R10 passing version)
// ============================================================================
#define T1N   256
#define T1DC  64
#define NCH   (DD/T1DC)       // 8
#define TILES 4
#define X1LD 264
#define X1F  (T1DC*X1LD)
#define C1LD 516
#define C1F  (KK*C1LD)
#define AS1LD 36
#define SM1_FLOATS (2*X1F + C1F + 64)
#define SM1_BYTES  (SM1_FLOATS*4)

__global__ __launch_bounds__(512, 1)
void k1_assign(const float* __restrict__ X,
               const float* __restrict__ CW,
               const float* __restrict__ scale)
{
    extern __shared__ float sm[];
    float* Xs0 = sm;
    float* Xs1 = Xs0 + X1F;
    float* Cs  = Xs1 + X1F;
    float* c2s = Cs + C1F;
    float* scs = c2s + 32;
    float* As  = Xs0;
    float* As2 = Xs1;
    float* x2p = Xs1 + 9216;

    const int t = threadIdx.x;
    const int w = t >> 5;
    const int b = blockIdx.y;
    const int tile_base = blockIdx.x * TILES;
    const float* Xb = X + (size_t)b * DD * NN;

    const int j  = t & 63;
    const int dr = t >> 6;
    const int nc = w & 7, half = w >> 3;

    float4 R[8];
    {
        const float* g = Xb + (size_t)dr * NN + tile_base * T1N + j * 4;
        #pragma unroll
        for (int r = 0; r < 8; ++r)
            R[r] = *(const float4*)(g + (size_t)(r * 8) * NN);
    }

    for (int i = t; i < KK * DD; i += 512) {
        int k = i >> 9, d = i & 511;
        Cs[k * C1LD + d] = wmma::__float_to_tf32(CW[i]);
    }
    if (t < 32) scs[t] = scale[t];
    __syncthreads();
    if (t < 32) {
        float s = 0.f;
        #pragma unroll 8
        for (int d = 0; d < DD; ++d) { float v = Cs[t * C1LD + d]; s += v * v; }
        c2s[t] = s;
    }

    wmma::fragment<wmma::accumulator, 16, 16, 8, float> p00, p01, p10, p11;
    wmma::fill_fragment(p00, 0.f); wmma::fill_fragment(p01, 0.f);
    wmma::fill_fragment(p10, 0.f); wmma::fill_fragment(p11, 0.f);
    float xa = 0.f, xb2 = 0.f, xc = 0.f, xd2 = 0.f;

    for (int u = 0; u < TILES * NCH; ++u) {
        const int c = u & 7;
        float* Xt = (u & 1) ? Xs1 : Xs0;

        #pragma unroll
        for (int r = 0; r < 8; ++r) {
            float4 v = R[r];
            xa += v.x * v.x; xb2 += v.y * v.y; xc += v.z * v.z; xd2 += v.w * v.w;
            *(float4*)&Xt[(r * 8 + dr) * X1LD + j * 4] = v;
        }
        if (u + 1 < TILES * NCH) {
            const int un = u + 1, tn = un >> 3, cn = un & 7;
            const float* g = Xb + (size_t)(cn * T1DC + dr) * NN
                           + (size_t)(tile_base + tn) * T1N + j * 4;
            #pragma unroll
            for (int r = 0; r < 8; ++r)
                R[r] = *(const float4*)(g + (size_t)(r * 8) * NN);
        }
        __syncthreads();

        #pragma unroll
        for (int ds4 = 0; ds4 < 4; ++ds4) {
            const int dl = half * 32 + ds4 * 8;
            const int dg = c * T1DC + dl;
            wmma::fragment<wmma::matrix_a, 16, 16, 8, wmma::precision::tf32, wmma::col_major> a0, a1;
            wmma::fragment<wmma::matrix_b, 16, 16, 8, wmma::precision::tf32, wmma::col_major> b0, b1;
            wmma::load_matrix_sync(a0, Xt + dl * X1LD + nc * 32,      X1LD);
            wmma::load_matrix_sync(a1, Xt + dl * X1LD + nc * 32 + 16, X1LD);
            wmma::load_matrix_sync(b0, Cs + dg,              C1LD);
            wmma::load_matrix_sync(b1, Cs + 16 * C1LD + dg,  C1LD);
            wmma::mma_sync(p00, a0, b0, p00);
            wmma::mma_sync(p01, a0, b1, p01);
            wmma::mma_sync(p10, a1, b0, p10);
            wmma::mma_sync(p11, a1, b1, p11);
        }

        if (c == NCH - 1) {
            const int tile = u >> 3;
            const int n0 = (tile_base + tile) * T1N;
            __syncthreads();

            *(float4*)&x2p[dr * X1LD + j * 4] = make_float4(xa, xb2, xc, xd2);
            float* dst = half ? As2 : As;
            wmma::store_matrix_sync(dst + (nc * 32) * AS1LD,           p00, AS1LD, wmma::mem_row_major);
            wmma::store_matrix_sync(dst + (nc * 32) * AS1LD + 16,      p01, AS1LD, wmma::mem_row_major);
            wmma::store_matrix_sync(dst + (nc * 32 + 16) * AS1LD,      p10, AS1LD, wmma::mem_row_major);
            wmma::store_matrix_sync(dst + (nc * 32 + 16) * AS1LD + 16, p11, AS1LD, wmma::mem_row_major);
            __syncthreads();

            {
                const int n = t >> 1, h = t & 1, ks = h * 16;
                float x2n = 0.f;
                #pragma unroll
                for (int r = 0; r < 8; ++r) x2n += x2p[r * X1LD + n];
                float sl[16];
                float m = -1e30f;
                #pragma unroll
                for (int jj = 0; jj < 16; ++jj) {
                    int k = ks + jj;
                    float xck = As[n * AS1LD + k] + As2[n * AS1LD + k];
                    float v = scs[k] * (x2n - 2.f * xck + c2s[k]);
                    sl[jj] = v; m = fmaxf(m, v);
                }
                m = fmaxf(m, __shfl_xor_sync(0xffffffffu, m, 1));
                float ssum = 0.f;
                #pragma unroll
                for (int jj = 0; jj < 16; ++jj) { sl[jj] = __expf(sl[jj] - m); ssum += sl[jj]; }
                ssum += __shfl_xor_sync(0xffffffffu, ssum, 1);
                const float inv = 1.0f / ssum;
                float4 o[4];
                #pragma unroll
                for (int jj = 0; jj < 16; ++jj)
                    ((float*)o)[jj] = wmma::__float_to_tf32(sl[jj] * inv);
                float4* dstA = (float4*)&A_buf[((size_t)b * NN + n0 + n) * KK + ks];
                dstA[0] = o[0]; dstA[1] = o[1]; dstA[2] = o[2]; dstA[3] = o[3];
            }
            __syncthreads();

            wmma::fill_fragment(p00, 0.f); wmma::fill_fragment(p01, 0.f);
            wmma::fill_fragment(p10, 0.f); wmma::fill_fragment(p11, 0.f);
            xa = xb2 = xc = xd2 = 0.f;
        }
    }
}

// ============================================================================
// Kernel 2 (DRAM-pattern fix): E[b,k,d] = sum_n A[b,n,k]*X[b,d,n] - S_k*c[k,d]
//   grid (16, 8), 256 threads, 1 CTA/SM. A-block [1024n x 32k] resident;
//   loop (8 d-chunks x 8 n-subtiles); X tiles [64d x 128n] -> 512B/row bursts.
//   Warp (khalf, dsub) holds one 16k x 16d accumulator per d-chunk (8 frags).
// ============================================================================
#define CHUNK2 1024
#define T2N    128
#define DCH    64
#define NDCH   (DD/DCH)        // 8
#define NSUB2  (CHUNK2/T2N)    // 8
#define ITERS  (NDCH*NSUB2)    // 64
#define ALD    36
#define ABLK_F (CHUNK2*ALD)    // 36864 floats (147456 B)
#define XLD    136             // == 8 (mod 32)
#define XT_F   (DCH*XLD)       // 8704 floats (34816 B) per buffer
#define SCR_LD 20
#define SCR_F  (8*16*SCR_LD)   // 2560 floats
#define SM2_FLOATS (ABLK_F + 2*XT_F + SCR_F + 8*32 + 32)
#define SM2_BYTES  (SM2_FLOATS*4)   // 228,608 B < 232,448 cap

__global__ __launch_bounds__(256)
void k2_aggregate(const float* __restrict__ X,
                  const float* __restrict__ CW,
                  float* __restrict__ out)
{
    extern __shared__ float sm[];
    float* Ablk = sm;                   // [1024][36]
    float* Xs0  = Ablk + ABLK_F;        // [64][136]
    float* Xs1  = Xs0 + XT_F;
    float* scr  = Xs1 + XT_F;           // [8 warps][16][20]
    float* Sp   = scr + SCR_F;          // [8][32]
    float* Ssm  = Sp + 8 * 32;          // [32]

    const int t = threadIdx.x;
    const int w = t >> 5;               // 0..7
    const int lane = t & 31;
    const int b = blockIdx.y;
    const int nbase = blockIdx.x * CHUNK2;
    const float* Xb = X + (size_t)b * DD * NN;
    const float* Ab = A_buf + (size_t)b * NN * KK;

    // warp role: khalf selects k in [khalf*16, +16), dsub selects d-sub of 16
    const int khalf = w >> 2;
    const int dsub  = w & 3;

    // X staging map: jx = n-quad (0..31) -> 512B contiguous per row per warp
    const int jx  = t & 31;
    const int dxr = t >> 5;             // 0..7

    auto stage = [&](int u) {
        const int dc = u >> 3, sub = u & 7;
        float* xd = (u & 1) ? Xs1 : Xs0;
        const float* g = Xb + (size_t)(dc * DCH) * NN + nbase + sub * T2N + jx * 4;
        #pragma unroll
        for (int r = 0; r < 8; ++r) {
            int dl = r * 8 + dxr;
            cp_async16(&xd[dl * XLD + jx * 4], g + (size_t)dl * NN);
        }
        cp_commit();
    };

    // ---- prologue: A-block (1 group) + X tiles 0,1 ----
    #pragma unroll
    for (int i = 0; i < 32; ++i) {
        int idx = t + i * 256;          // 8192 quads total
        int row = idx >> 3, q = idx & 7;
        cp_async16(&Ablk[row * ALD + q * 4], Ab + (size_t)(nbase + row) * KK + q * 4);
    }
    cp_commit();
    stage(0);
    stage(1);

    wmma::fragment<wmma::accumulator, 16, 16, 8, float> eacc[NDCH];
    #pragma unroll
    for (int dc = 0; dc < NDCH; ++dc) wmma::fill_fragment(eacc[dc], 0.f);

    // ---- mainloop: 8 d-chunks x 8 n-subtiles ----
    #pragma unroll
    for (int dc = 0; dc < NDCH; ++dc) {
        for (int sub = 0; sub < NSUB2; ++sub) {
            const int u = dc * NSUB2 + sub;
            if (u + 1 < ITERS) cp_wait<1>(); else cp_wait<0>();
            __syncthreads();
            float* Xt = (u & 1) ? Xs1 : Xs0;

            #pragma unroll
            for (int st = 0; st < 16; ++st) {
                wmma::fragment<wmma::matrix_a, 16, 16, 8, wmma::precision::tf32, wmma::col_major> af;
                wmma::fragment<wmma::matrix_b, 16, 16, 8, wmma::precision::tf32, wmma::col_major> bf;
                wmma::load_matrix_sync(af, Ablk + (sub * T2N + st * 8) * ALD + khalf * 16, ALD);
                wmma::load_matrix_sync(bf, Xt + (dsub * 16) * XLD + st * 8, XLD);
                wmma::mma_sync(eacc[dc], af, bf, eacc[dc]);
            }
            __syncthreads();
            if (u + 2 < ITERS) stage(u + 2);
        }
    }

    // ---- S_k from resident A-block: warp w sums rows [w*128, +128) ----
    {
        float acc = 0.f;
        #pragma unroll 8
        for (int n = 0; n < 128; ++n) acc += Ablk[(w * 128 + n) * ALD + lane];
        Sp[w * 32 + lane] = acc;
    }
    __syncthreads();
    if (t < 32) {
        float s = 0.f;
        #pragma unroll
        for (int ww = 0; ww < 8; ++ww) s += Sp[ww * 32 + t];
        Ssm[t] = s;
    }
    __syncthreads();

    // ---- epilogue: per-d-chunk frag dump + fold correction + atomicAdd ----
    float* myscr = scr + w * 16 * SCR_LD;
    float* op = out + (size_t)b * KK * DD;
    #pragma unroll
    for (int dc = 0; dc < NDCH; ++dc) {
        wmma::store_matrix_sync(myscr, eacc[dc], SCR_LD, wmma::mem_row_major);
        __syncwarp();
        #pragma unroll
        for (int e = 0; e < 8; ++e) {
            int idx = lane + e * 32;        // 256 elements: 16k x 16d
            int i = idx >> 4, jj = idx & 15;
            int k = khalf * 16 + i;
            int d = dc * DCH + dsub * 16 + jj;
            float v = myscr[i * SCR_LD + jj] - Ssm[k] * CW[k * DD + d];
            atomicAdd(&op[k * DD + d], v);
        }
        __syncwarp();
    }
}

// ============================================================================
extern "C" void kernel_launch(void* const* d_in, const int* in_sizes, int n_in,
                              void* d_out, int out_size) {
    (void)in_sizes; (void)n_in;
    const float* X     = (const float*)d_in[0];
    const float* CW    = (const float*)d_in[1];
    const float* scale = (const float*)d_in[2];
    float* out = (float*)d_out;

    cudaFuncSetAttribute(k1_assign,    cudaFuncAttributeMaxDynamicSharedMemorySize, SM1_BYTES);
    cudaFuncSetAttribute(k2_aggregate, cudaFuncAttributeMaxDynamicSharedMemorySize, SM2_BYTES);

    cudaMemsetAsync(d_out, 0, (size_t)out_size * sizeof(float));

    dim3 g1(NN / (T1N * TILES), BB);   // 16 x 8 = 128 CTAs (persistent, 4 tiles)
    k1_assign<<<g1, 512, SM1_BYTES>>>(X, CW, scale);

    dim3 g2(NN / CHUNK2, BB);          // 16 x 8 = 128 CTAs
    k2_aggregate<<<g2, 256, SM2_BYTES>>>(X, CW, out);
}

// round 13
// speedup vs baseline: 1.1028x; 1.1028x over previous
#include <cuda_runtime.h>
#include <mma.h>
#include <cstdint>

using namespace nvcuda;

#define BB 8
#define DD 512
#define KK 32
#define NN 16384

#define TN    32              // pixels per tile
#define NT    16              // tiles per CTA
#define CHUNK (TN*NT)         // 512 pixels per CTA

// SMEM pitches (floats)
#define CSLD 516              // == 4 (mod 32): conflict-free matrix_b (GEMM1)
#define XLD  36               // == 4 (mod 32): conflict-free matrix_b (GEMM2)
#define ALD  40               // == 8 (mod 32): conflict-free matrix_a (GEMM2)
#define ESLD 516              // R12 bug: was 260; Es rows hold all 512 d

#define CS_F (KK*CSLD)        // 16512 (== 32*ESLD: exact alias for Es)
#define X_F  (DD*XLD)         // 18432 per buffer
#define A_F  (TN*ALD)         // 1280 per buffer
#define SMEM_FLOATS (CS_F + 2*X_F + 2*A_F + 256 + 96)
#define SMEM_BYTES  (SMEM_FLOATS*4)   // 225,152 B < 232,448 cap

__device__ __forceinline__ void cp_async16(void* smem_dst, const void* gmem_src) {
    uint32_t s = (uint32_t)__cvta_generic_to_shared(smem_dst);
    asm volatile("cp.async.cg.shared.global [%0], [%1], 16;\n" :: "r"(s), "l"(gmem_src));
}
__device__ __forceinline__ void cp_commit() {
    asm volatile("cp.async.commit_group;\n" ::: "memory");
}
template<int N>
__device__ __forceinline__ void cp_wait() {
    asm volatile("cp.async.wait_group %0;\n" :: "n"(N) : "memory");
}

// ============================================================================
// Fused kernel: per 32-pixel tile —
//   stage X[512d x 32n] (cp.async, double-buffered)
//   GEMM1 (warps 0-7) || x^2 (warps 8-15)
//   softmax (A stays in SMEM; never written to DRAM)
//   GEMM2 into persistent accumulators
// E[b,k,d] = sum_n A[n,k] X[d,n] - S_k c[k,d], atomicAdd epilogue.
// ============================================================================
__global__ __launch_bounds__(512, 1)
void enc_fused(const float* __restrict__ X,
               const float* __restrict__ CW,
               const float* __restrict__ scale,
               float* __restrict__ out)
{
    extern __shared__ float sm[];
    float* Cs  = sm;               // [32][516] tf32-rounded codewords
    float* Xs0 = Cs + CS_F;        // [512][36]
    float* Xs1 = Xs0 + X_F;        // [512][36]
    float* As0 = Xs1 + X_F;        // [32][40] P partial (d-half 0) -> A in place
    float* As1 = As0 + A_F;        // [32][40] P partial (d-half 1)
    float* x2p = As1 + A_F;        // [8][32]
    float* c2s = x2p + 256;        // [32]
    float* scs = c2s + 32;         // [32]
    float* Ssm = scs + 32;         // [32]
    float* Es  = sm;               // epilogue alias (Cs dead): [32][516]

    const int t = threadIdx.x;
    const int w = t >> 5;
    const int lane = t & 31;
    const int b = blockIdx.y;
    const int nbase = blockIdx.x * CHUNK;
    const float* Xb = X + (size_t)b * DD * NN;

    // staging map: jx = n-quad (0..7), dxr = d-row in group of 64
    const int jx = t & 7;
    const int dxr = t >> 3;

    auto stage = [&](int u) {
        float* xd = (u & 1) ? Xs1 : Xs0;
        const float* g = Xb + nbase + u * TN + jx * 4;
        #pragma unroll
        for (int r = 0; r < 8; ++r) {
            int d = r * 64 + dxr;
            cp_async16(&xd[d * XLD + jx * 4], g + (size_t)d * NN);
        }
        cp_commit();
    };

    // get DRAM going first, then prologue compute under the loads
    stage(0);
    stage(1);

    for (int i = t; i < KK * DD; i += 512) {
        int k = i >> 9, d = i & 511;
        Cs[k * CSLD + d] = wmma::__float_to_tf32(CW[i]);
    }
    if (t < 32) { scs[t] = scale[t]; Ssm[t] = 0.f; }
    __syncthreads();
    {   // c2s spread over 512 threads: k = t>>4, part = t&15, 32 d each
        const int k = t >> 4, part = t & 15;
        float s = 0.f;
        #pragma unroll
        for (int jj = 0; jj < 32; ++jj) {
            float v = Cs[k * CSLD + part * 32 + jj];
            s += v * v;
        }
        s += __shfl_xor_sync(0xffffffffu, s, 1);
        s += __shfl_xor_sync(0xffffffffu, s, 2);
        s += __shfl_xor_sync(0xffffffffu, s, 4);
        s += __shfl_xor_sync(0xffffffffu, s, 8);
        if (part == 0) c2s[k] = s;   // consumed after later barriers
    }

    // persistent GEMM2 accumulators: warp w owns d in [w*32, +32), all 32 k
    wmma::fragment<wmma::accumulator, 16, 16, 8, float> eacc[2][2];
    #pragma unroll
    for (int kc = 0; kc < 2; ++kc)
        #pragma unroll
        for (int dt = 0; dt < 2; ++dt)
            wmma::fill_fragment(eacc[kc][dt], 0.f);

    const int q = t & 15;            // softmax k-pair slot
    float sacc0 = 0.f, sacc1 = 0.f;  // S_k partials for k = 2q, 2q+1

    for (int u = 0; u < NT; ++u) {
        if (u + 1 < NT) cp_wait<1>(); else cp_wait<0>();
        __syncthreads();
        float* Xt = (u & 1) ? Xs1 : Xs0;

        if (w < 8) {
            // ---- GEMM1 (warps 0-7): warp = (nc, kc, dh); d-range 256 ----
            const int nc = w & 1, kc = (w >> 1) & 1, dh = w >> 2;
            wmma::fragment<wmma::accumulator, 16, 16, 8, float> p;
            wmma::fill_fragment(p, 0.f);
            #pragma unroll 8
            for (int st = 0; st < 32; ++st) {
                const int d = dh * 256 + st * 8;
                wmma::fragment<wmma::matrix_a, 16, 16, 8, wmma::precision::tf32, wmma::col_major> a;
                wmma::fragment<wmma::matrix_b, 16, 16, 8, wmma::precision::tf32, wmma::col_major> bf;
                wmma::load_matrix_sync(a,  Xt + d * XLD + nc * 16, XLD);
                wmma::load_matrix_sync(bf, Cs + kc * 16 * CSLD + d, CSLD);
                wmma::mma_sync(p, a, bf, p);
            }
            float* dst = dh ? As1 : As0;
            wmma::store_matrix_sync(dst + nc * 16 * ALD + kc * 16, p, ALD, wmma::mem_row_major);
        } else {
            // ---- x^2 (warps 8-15): thread (n, dp) sums 64 d ----
            const int tt = t - 256, n = tt & 31, dp = tt >> 5;
            float acc = 0.f;
            #pragma unroll 16
            for (int r = 0; r < 64; ++r) {
                float v = Xt[(dp * 64 + r) * XLD + n];
                acc += v * v;
            }
            x2p[dp * 32 + n] = acc;
        }
        __syncthreads();

        // ---- softmax: 16 threads per pixel, 2 k each; A in place in As0 ----
        {
            const int n = t >> 4;
            float x2n = 0.f;
            #pragma unroll
            for (int r = 0; r < 8; ++r) x2n += x2p[r * 32 + n];
            const int k0 = q * 2;
            float p0 = As0[n * ALD + k0]     + As1[n * ALD + k0];
            float p1 = As0[n * ALD + k0 + 1] + As1[n * ALD + k0 + 1];
            float l0 = scs[k0]     * (x2n - 2.f * p0 + c2s[k0]);
            float l1 = scs[k0 + 1] * (x2n - 2.f * p1 + c2s[k0 + 1]);
            float m = fmaxf(l0, l1);
            m = fmaxf(m, __shfl_xor_sync(0xffffffffu, m, 1));
            m = fmaxf(m, __shfl_xor_sync(0xffffffffu, m, 2));
            m = fmaxf(m, __shfl_xor_sync(0xffffffffu, m, 4));
            m = fmaxf(m, __shfl_xor_sync(0xffffffffu, m, 8));
            float e0 = __expf(l0 - m), e1 = __expf(l1 - m);
            float ss = e0 + e1;
            ss += __shfl_xor_sync(0xffffffffu, ss, 1);
            ss += __shfl_xor_sync(0xffffffffu, ss, 2);
            ss += __shfl_xor_sync(0xffffffffu, ss, 4);
            ss += __shfl_xor_sync(0xffffffffu, ss, 8);
            const float inv = 1.0f / ss;
            float a0v = e0 * inv, a1v = e1 * inv;
            sacc0 += a0v; sacc1 += a1v;
            As0[n * ALD + k0]     = a0v;   // raw fp32; HMMA truncates to tf32
            As0[n * ALD + k0 + 1] = a1v;
        }
        __syncthreads();

        // ---- GEMM2 (all 16 warps): E[k][d] += sum_n A[n][k] * X[d][n] ----
        #pragma unroll
        for (int ns = 0; ns < 4; ++ns) {
            wmma::fragment<wmma::matrix_a, 16, 16, 8, wmma::precision::tf32, wmma::col_major> a2[2];
            wmma::load_matrix_sync(a2[0], As0 + ns * 8 * ALD,      ALD);
            wmma::load_matrix_sync(a2[1], As0 + ns * 8 * ALD + 16, ALD);
            #pragma unroll
            for (int dt = 0; dt < 2; ++dt) {
                wmma::fragment<wmma::matrix_b, 16, 16, 8, wmma::precision::tf32, wmma::col_major> b2;
                wmma::load_matrix_sync(b2, Xt + (w * 32 + dt * 16) * XLD + ns * 8, XLD);
                wmma::mma_sync(eacc[0][dt], a2[0], b2, eacc[0][dt]);
                wmma::mma_sync(eacc[1][dt], a2[1], b2, eacc[1][dt]);
            }
        }
        __syncthreads();                     // buffer u free; As/x2p consumed
        if (u + 2 < NT) stage(u + 2);        // refill freed buffer
    }

    // ---- S_k fold: lanes l and l+16 share q ----
    sacc0 += __shfl_xor_sync(0xffffffffu, sacc0, 16);
    sacc1 += __shfl_xor_sync(0xffffffffu, sacc1, 16);
    if (lane < 16) {
        atomicAdd(&Ssm[q * 2],     sacc0);
        atomicAdd(&Ssm[q * 2 + 1], sacc1);
    }

    // ---- epilogue: dump accumulators (alias Cs region), fold, atomicAdd ----
    #pragma unroll
    for (int kc = 0; kc < 2; ++kc)
        #pragma unroll
        for (int dt = 0; dt < 2; ++dt)
            wmma::store_matrix_sync(Es + kc * 16 * ESLD + w * 32 + dt * 16,
                                    eacc[kc][dt], ESLD, wmma::mem_row_major);
    __syncthreads();

    float* op = out + (size_t)b * KK * DD;
    for (int i = t; i < KK * DD; i += 512) {
        int k = i >> 9, d = i & 511;
        float v = Es[k * ESLD + d] - Ssm[k] * CW[i];   // exact c in correction
        atomicAdd(&op[i], v);
    }
}

// ============================================================================
extern "C" void kernel_launch(void* const* d_in, const int* in_sizes, int n_in,
                              void* d_out, int out_size) {
    (void)in_sizes; (void)n_in;
    const float* X     = (const float*)d_in[0];
    const float* CW    = (const float*)d_in[1];
    const float* scale = (const float*)d_in[2];
    float* out = (float*)d_out;

    cudaFuncSetAttribute(enc_fused, cudaFuncAttributeMaxDynamicSharedMemorySize, SMEM_BYTES);

    // d_out is poisoned; atomics need zero init (graph-capturable memset node)
    cudaMemsetAsync(d_out, 0, (size_t)out_size * sizeof(float));

    dim3 grid(NN / CHUNK, BB);   // 32 x 8 = 256 CTAs
    enc_fused<<<grid, 512, SMEM_BYTES>>>(X, CW, scale, out);
}